// round 14
// baseline (speedup 1.0000x reference)
#include <cuda_runtime.h>
#include <math.h>
#include <cstdint>

// ---------------- problem constants ----------------
#define Bn   256
#define Tn   512
#define INn  32
#define Hn   128
#define Sn   4
#define HQn  32
#define BTn  (Bn*Tn)          // 131072 positions
#define DTC  0.1f
#define LOG2E 1.4426950408889634f

typedef unsigned long long u64;
typedef unsigned int u32;
typedef ulonglong2 u64x2;

// ---------------- scratch (static device globals; no allocation) ----------------
__device__ float g_xp  [(size_t)BTn*Hn];        //  64 MB
__device__ float g_inp [(size_t)Sn*BTn*Hn];     // 268 MB (pair-interleaved channels)
__device__ float g_itau[(size_t)Sn*BTn*Hn];     // 268 MB (pair-interleaved channels)
__device__ float g_hT  [Sn*Bn*Hn];

// ---------------- packed fp32x2 helpers (Blackwell FFMA2) ----------------
__device__ __forceinline__ void ffma2(u64 &d, u64 a, u64 b) {
    asm("fma.rn.f32x2 %0, %1, %2, %0;" : "+l"(d) : "l"(a), "l"(b));
}
__device__ __forceinline__ void add2(u64 &d, u64 a) {
    asm("add.rn.f32x2 %0, %0, %1;" : "+l"(d) : "l"(a));
}
__device__ __forceinline__ float hsum1(u64 a0) {
    float x0, y0;
    asm("mov.b64 {%0,%1}, %2;" : "=f"(x0), "=f"(y0) : "l"(a0));
    return x0 + y0;
}
__device__ __forceinline__ float hsum2p(u64 a0, u64 a1) {
    add2(a0, a1);
    return hsum1(a0);
}
__device__ __forceinline__ float hsum4(u64 a0, u64 a1, u64 a2, u64 a3) {
    add2(a0, a1); add2(a2, a3); add2(a0, a2);
    return hsum1(a0);
}

// ---------------- fast approx math ----------------
__device__ __forceinline__ float fast_ex2(float x) {
    float r; asm("ex2.approx.f32 %0, %1;" : "=f"(r) : "f"(x)); return r;
}
__device__ __forceinline__ float fast_rcp(float x) {
    float r; asm("rcp.approx.f32 %0, %1;" : "=f"(r) : "f"(x)); return r;
}
__device__ __forceinline__ float fast_sqrt(float x) {
    float r; asm("sqrt.approx.f32 %0, %1;" : "=f"(r) : "f"(x)); return r;
}
// single-op MUFU tanh (sm_75+): ~16cy, abs err ~6e-4
__device__ __forceinline__ float tanh_mufu(float x) {
    float r; asm("tanh.approx.f32 %0, %1;" : "=f"(r) : "f"(x)); return r;
}
__device__ __forceinline__ float fast_sigmoid(float z) {
    float zc = fminf(fmaxf(z, -30.f), 30.f);
    return fast_rcp(1.f + fast_ex2(-zc * LOG2E));
}

// ============================================================================
// K1: x_proj[pos, i] = x[pos, :32] @ Wp[i, :32] + bp[i]
// ============================================================================
__global__ void __launch_bounds__(128) k_xp(const float* __restrict__ x,
                                            const float* __restrict__ Wp,
                                            const float* __restrict__ bp) {
    const int i  = threadIdx.x;
    const int p0 = blockIdx.x * 32;
    __shared__ __align__(16) float xs[32][INn];

    const float4* src = (const float4*)(x + (size_t)p0 * INn);
    float4* dst = (float4*)&xs[0][0];
    dst[i]       = src[i];
    dst[i + 128] = src[i + 128];

    u64 w[16];
    {
        const u64x2* wq = (const u64x2*)(Wp + (size_t)i * INn);
#pragma unroll
        for (int m = 0; m < 8; m++) { u64x2 v = wq[m]; w[2*m] = v.x; w[2*m+1] = v.y; }
    }
    const float bias = bp[i];
    __syncthreads();

#pragma unroll 4
    for (int p = 0; p < 32; p++) {
        const u64x2* xq = (const u64x2*)&xs[p][0];
        u64 a0 = 0ull, a1 = 0ull, a2 = 0ull, a3 = 0ull;
#pragma unroll
        for (int m = 0; m < 8; m += 2) {
            u64x2 p0v = xq[m], p1v = xq[m+1];
            ffma2(a0, w[2*m],   p0v.x); ffma2(a1, w[2*m+1], p0v.y);
            ffma2(a2, w[2*m+2], p1v.x); ffma2(a3, w[2*m+3], p1v.y);
        }
        g_xp[(size_t)(p0 + p) * Hn + i] = hsum4(a0, a1, a2, a3) + bias;
    }
}

// ============================================================================
// K2: inp drive, split-K dual-channel (measured best, R9). Pair-interleaved
// output: slots (2c, 2c+1) hold channels (c, c+64).
// ============================================================================
__global__ void __launch_bounds__(128) k_inp(const float* __restrict__ Win_w,
                                             const float* __restrict__ Win_b,
                                             const float* __restrict__ cbias) {
    const int i    = threadIdx.x;
    const int s    = blockIdx.y;
    const int p0   = blockIdx.x * 64;
    const int wd   = i >> 5;
    const int lane = i & 31;
    const int half = lane >> 4;
    const int c    = wd * 16 + (lane & 15);   // 0..63
    __shared__ __align__(16) float xs[64][Hn];   // 32 KB

    const float4* src = (const float4*)(g_xp + (size_t)p0 * Hn);
    float4* dst = (float4*)&xs[0][0];
#pragma unroll
    for (int r = i; r < 2048; r += 128) dst[r] = src[r];

    u64 wA[32], wB[32];
    {
        const u64x2* wqA = (const u64x2*)(Win_w + ((size_t)s * Hn + c) * Hn + half * 64);
        const u64x2* wqB = (const u64x2*)(Win_w + ((size_t)s * Hn + c + 64) * Hn + half * 64);
#pragma unroll
        for (int m = 0; m < 16; m++) { u64x2 v = wqA[m]; wA[2*m] = v.x; wA[2*m+1] = v.y; }
#pragma unroll
        for (int m = 0; m < 16; m++) { u64x2 v = wqB[m]; wB[2*m] = v.x; wB[2*m+1] = v.y; }
    }
    const float biasA = Win_b[s * Hn + c]      + cbias[s * Hn + c];
    const float biasB = Win_b[s * Hn + c + 64] + cbias[s * Hn + c + 64];
    __syncthreads();

    float* outp = g_inp + ((size_t)s * BTn + p0) * Hn + 2 * c;
#pragma unroll 2
    for (int p = 0; p < 64; p++) {
        const u64x2* xq = (const u64x2*)(&xs[p][half * 64]);
        u64 a0 = 0ull, a1 = 0ull, b0 = 0ull, b1 = 0ull;
#pragma unroll
        for (int m = 0; m < 16; m++) {
            const u64x2 hv = xq[m];
            ffma2(a0, wA[2*m],   hv.x); ffma2(b0, wB[2*m],   hv.x);
            ffma2(a1, wA[2*m+1], hv.y); ffma2(b1, wB[2*m+1], hv.y);
        }
        float pA = hsum2p(a0, a1);
        float pB = hsum2p(b0, b1);
        pA += __shfl_xor_sync(0xffffffffu, pA, 16);
        pB += __shfl_xor_sync(0xffffffffu, pB, 16);
        if (half == 0) {
            float2 v = make_float2(pA + biasA, pB + biasB);
            __stwt((float2*)(outp + (size_t)p * Hn), v);
        }
    }
}

// ============================================================================
// K3: volatility gate -> itau (R9 structure, pair-interleaved output).
// ============================================================================
__global__ void __launch_bounds__(128) k_itau(const float* __restrict__ v1w,
                                              const float* __restrict__ v1b,
                                              const float* __restrict__ v2w,
                                              const float* __restrict__ v2b,
                                              const float* __restrict__ tau_base) {
    const int i    = threadIdx.x;
    const int s    = blockIdx.y;
    const int p0   = blockIdx.x * 64;
    const int wd   = i >> 5;
    const int lane = i & 31;
    __shared__ __align__(16) float xs[64][Hn];   // 32 KB
    __shared__ __align__(16) float gs[64][HQn];  //  8 KB

    const float4* src = (const float4*)(g_xp + (size_t)p0 * Hn);
    float4* dst = (float4*)&xs[0][0];
#pragma unroll
    for (int r = i; r < 2048; r += 128) dst[r] = src[r];
    __syncthreads();

    // ---- stage 1: g = relu(xp @ v1w.T + v1b), split-K dual-output ----
    {
        const int half = lane >> 4;
        const int q    = lane & 15;
        u64 wA[32], wB[32];
        const u64x2* wqA = (const u64x2*)(v1w + ((size_t)s * HQn + q) * Hn + half * 64);
        const u64x2* wqB = (const u64x2*)(v1w + ((size_t)s * HQn + q + 16) * Hn + half * 64);
#pragma unroll
        for (int m = 0; m < 16; m++) { u64x2 v = wqA[m]; wA[2*m] = v.x; wA[2*m+1] = v.y; }
#pragma unroll
        for (int m = 0; m < 16; m++) { u64x2 v = wqB[m]; wB[2*m] = v.x; wB[2*m+1] = v.y; }
        const float b1A = v1b[s * HQn + q];
        const float b1B = v1b[s * HQn + q + 16];
#pragma unroll 2
        for (int pp = 0; pp < 16; pp++) {
            const int p = wd * 16 + pp;
            const u64x2* xq = (const u64x2*)(&xs[p][half * 64]);
            u64 a0 = 0ull, a1 = 0ull, b0 = 0ull, b1 = 0ull;
#pragma unroll
            for (int m = 0; m < 16; m++) {
                const u64x2 hv = xq[m];
                ffma2(a0, wA[2*m],   hv.x); ffma2(b0, wB[2*m],   hv.x);
                ffma2(a1, wA[2*m+1], hv.y); ffma2(b1, wB[2*m+1], hv.y);
            }
            float pA = hsum2p(a0, a1);
            float pB = hsum2p(b0, b1);
            pA += __shfl_xor_sync(0xffffffffu, pA, 16);
            pB += __shfl_xor_sync(0xffffffffu, pB, 16);
            if (half == 0) {
                gs[p][q]      = fmaxf(pA + b1A, 0.f);
                gs[p][q + 16] = fmaxf(pB + b1B, 0.f);
            }
        }
    }
    __syncthreads();

    // ---- stage 2: vol -> itau (channel-permuted, coalesced store) ----
    {
        const int c = ((i & 1) << 6) | (i >> 1);
        u64 w2[16];
        const u64x2* wq = (const u64x2*)(v2w + ((size_t)s * Hn + c) * HQn);
#pragma unroll
        for (int m = 0; m < 8; m++) { u64x2 v = wq[m]; w2[2*m] = v.x; w2[2*m+1] = v.y; }
        const float b2 = v2b[s * Hn + c];
        const float tb = tau_base[s * Hn + c];
        float* outp = g_itau + ((size_t)s * BTn + p0) * Hn + i;
#pragma unroll 2
        for (int p = 0; p < 64; p++) {
            const u64x2* gq = (const u64x2*)&gs[p][0];
            u64 a0 = 0ull, a1 = 0ull, a2 = 0ull, a3 = 0ull;
#pragma unroll
            for (int m = 0; m < 8; m += 2) {
                u64x2 p0v = gq[m], p1v = gq[m+1];
                ffma2(a0, w2[2*m],   p0v.x); ffma2(a1, w2[2*m+1], p0v.y);
                ffma2(a2, w2[2*m+2], p1v.x); ffma2(a3, w2[2*m+3], p1v.y);
            }
            const float z   = hsum4(a0, a1, a2, a3) + b2;
            const float vol = fast_sigmoid(z);
            float tau = tb * (0.2f + 1.8f * (1.f - vol));
            tau = fminf(fmaxf(tau, 0.1f), 10.f);
            __stwt(outp + (size_t)p * Hn, 1.f / tau);
        }
    }
}

// ============================================================================
// K4: liquid-cell scan, quarter-K x 4 channels per thread, conflict-free.
// Thread (warp wd, lane l): q = l&3 (K-quarter), cb = wd*8 + (l>>2).
// Owns channels {cb, cb+32, cb+64, cb+96}; holds 4 quarter-rows of Wrec
// (128 floats = 64 u64 regs). h lives in 4 PADDED segments of 36 floats
// (144B stride): quarter q reads seg q -> the 4 addresses per LDS hit
// DISJOINT bank groups {0,4,8,12}+4m (fixes the R3/R7 same-bank bug),
// and only 8 LDS.128/thread/step -> smem->RF return wavefronts HALVED vs
// R9 (the measured wall: 768cy/step == step time).
// Quarter combine over shfl offsets {1,2}; norm over {4,8,16}.
// ============================================================================
__global__ void __launch_bounds__(128, 3) k_scan(const float* __restrict__ Wrec) {
    const int bid  = blockIdx.x;
    const int s    = 3 - (bid >> 8);     // heavy scale first (LPT)
    const int b    = bid & 255;
    const int t    = threadIdx.x;
    const int wd   = t >> 5;
    const int lane = t & 31;
    const int q    = lane & 3;               // K-quarter
    const int cb   = wd * 8 + (lane >> 2);   // base channel 0..31

    __shared__ __align__(16) float h_s[4 * 36];   // 4 padded segments (144B stride)
    __shared__ __align__(16) float red[4];

    // weights: 4 rows (cb+32r), K-quarter cols [q*32, q*32+32) -- contiguous
    u64 w[4][16];
    {
        const float* Wb = Wrec + (size_t)s * Hn * Hn + q * 32;
#pragma unroll
        for (int r = 0; r < 4; r++) {
            const u64x2* wq = (const u64x2*)(Wb + (size_t)(cb + 32 * r) * Hn);
#pragma unroll
            for (int m = 0; m < 8; m++) { u64x2 v = wq[m]; w[r][2*m] = v.x; w[r][2*m+1] = v.y; }
        }
    }

    float h0 = 0.f, h1 = 0.f, h2 = 0.f, h3 = 0.f;   // channels cb, cb+32, cb+64, cb+96
    for (int z = t; z < 4 * 36; z += 128) h_s[z] = 0.f;   // zero ALL 144 (incl. padding)
    const int nsteps = 3 + 2 * s;
    // pair-interleaved drive: float2 idx cb -> (cb, cb+64); idx cb+32 -> (cb+32, cb+96)
    const float2* inp_p  = (const float2*)g_inp  + ((size_t)(s * Bn + b)) * Tn * 64;
    const float2* itau_p = (const float2*)g_itau + ((size_t)(s * Bn + b)) * Tn * 64;
    __syncthreads();

    float2 iA = __ldcs(inp_p + cb);         // (c0, c2)
    float2 iB = __ldcs(inp_p + cb + 32);    // (c1, c3)
    float2 tA = __ldcs(itau_p + cb);
    float2 tB = __ldcs(itau_p + cb + 32);
    for (int tt = 0; tt < Tn; tt++) {
        const int tn = (tt + 1 < Tn) ? tt + 1 : tt;
        const float2 niA = __ldcs(inp_p  + (size_t)tn * 64 + cb);
        const float2 niB = __ldcs(inp_p  + (size_t)tn * 64 + cb + 32);
        const float2 ntA = __ldcs(itau_p + (size_t)tn * 64 + cb);
        const float2 ntB = __ldcs(itau_p + (size_t)tn * 64 + cb + 32);

        for (int k = 0; k < nsteps; k++) {
            // partial dots: this thread's 32 h-values (seg q), 4 output rows
            const u64x2* hq = (const u64x2*)(h_s + q * 36);
            u64 a0 = 0ull, a1 = 0ull, a2 = 0ull, a3 = 0ull;
            u64 b0 = 0ull, b1 = 0ull, b2 = 0ull, b3 = 0ull;
#pragma unroll
            for (int m = 0; m < 8; m++) {
                const u64x2 hv = hq[m];
                ffma2(a0, w[0][2*m],   hv.x); ffma2(a1, w[1][2*m],   hv.x);
                ffma2(a2, w[2][2*m],   hv.x); ffma2(a3, w[3][2*m],   hv.x);
                ffma2(b0, w[0][2*m+1], hv.y); ffma2(b1, w[1][2*m+1], hv.y);
                ffma2(b2, w[2][2*m+1], hv.y); ffma2(b3, w[3][2*m+1], hv.y);
            }
            float p0 = hsum2p(a0, b0);
            float p1 = hsum2p(a1, b1);
            float p2 = hsum2p(a2, b2);
            float p3 = hsum2p(a3, b3);
            // combine 4 K-quarters over lane bits 0,1 (shfl offsets 1, 2)
            p0 += __shfl_xor_sync(0xffffffffu, p0, 1);
            p1 += __shfl_xor_sync(0xffffffffu, p1, 1);
            p2 += __shfl_xor_sync(0xffffffffu, p2, 1);
            p3 += __shfl_xor_sync(0xffffffffu, p3, 1);
            p0 += __shfl_xor_sync(0xffffffffu, p0, 2);
            p1 += __shfl_xor_sync(0xffffffffu, p1, 2);
            p2 += __shfl_xor_sync(0xffffffffu, p2, 2);
            p3 += __shfl_xor_sync(0xffffffffu, p3, 2);

            const float dh0 = (tanh_mufu(p0 + iA.x) - h0) * tA.x;
            const float dh1 = (tanh_mufu(p1 + iB.x) - h1) * tB.x;
            const float dh2 = (tanh_mufu(p2 + iA.y) - h2) * tA.y;
            const float dh3 = (tanh_mufu(p3 + iB.y) - h3) * tB.y;

            // ||dhdt||^2: q-lanes duplicate -> reduce over cw bits {4,8,16}
            float sq = fmaf(dh0, dh0, fmaf(dh1, dh1, fmaf(dh2, dh2, dh3 * dh3)));
            sq += __shfl_xor_sync(0xffffffffu, sq, 4);
            sq += __shfl_xor_sync(0xffffffffu, sq, 8);
            sq += __shfl_xor_sync(0xffffffffu, sq, 16);
            if (lane == 0) red[wd] = sq;
            __syncthreads();
            const float4 r4 = *(const float4*)red;
            const float mag = fast_sqrt((r4.x + r4.y) + (r4.z + r4.w));
            const float sc  = DTC * fast_rcp(fmaf(0.2f, mag, 1.f));
            h0 = fmaf(sc, dh0, h0);
            h1 = fmaf(sc, dh1, h1);
            h2 = fmaf(sc, dh2, h2);
            h3 = fmaf(sc, dh3, h3);
            if (q == 0) {
                h_s[0 * 36 + cb] = h0;
                h_s[1 * 36 + cb] = h1;
                h_s[2 * 36 + cb] = h2;
                h_s[3 * 36 + cb] = h3;
            }
            __syncthreads();
        }
        iA = niA; iB = niB; tA = ntA; tB = ntB;
    }
    if (q == 0) {
        float* o = g_hT + ((size_t)(s * Bn + b)) * Hn;
        o[cb]      = h0;
        o[cb + 32] = h1;
        o[cb + 64] = h2;
        o[cb + 96] = h3;
    }
}

// ============================================================================
// K5: projection heads + fusion MLP. One CTA per batch row.
// ============================================================================
__global__ void __launch_bounds__(128) k_head(const float* __restrict__ proj_w,
                                              const float* __restrict__ proj_b,
                                              const float* __restrict__ f1_w,
                                              const float* __restrict__ f1_b,
                                              const float* __restrict__ f2_w,
                                              const float* __restrict__ f2_b,
                                              const float* __restrict__ f3_w,
                                              const float* __restrict__ f3_b,
                                              float* __restrict__ out) {
    const int b = blockIdx.x;
    const int i = threadIdx.x;
    __shared__ float fs[Hn];
    __shared__ float h1s[Hn];
    __shared__ float h2s[64];
    __shared__ float rs[4];

    {
        const int s = i >> 5, q = i & 31;
        const float* hrow = g_hT + (size_t)(s * Bn + b) * Hn;
        const float* pw   = proj_w + (size_t)(s * 32 + q) * Hn;
        float acc = proj_b[s * 32 + q];
#pragma unroll 8
        for (int j = 0; j < Hn; j++) acc += hrow[j] * pw[j];
        fs[i] = acc;
    }
    __syncthreads();

    {
        const float* w1 = f1_w + (size_t)i * Hn;
        float acc = f1_b[i];
#pragma unroll 8
        for (int j = 0; j < Hn; j++) acc += fs[j] * w1[j];
        h1s[i] = fmaxf(acc, 0.f);
    }
    __syncthreads();

    if (i < 64) {
        const float* w2 = f2_w + (size_t)i * Hn;
        float acc = f2_b[i];
#pragma unroll 8
        for (int j = 0; j < Hn; j++) acc += h1s[j] * w2[j];
        h2s[i] = fmaxf(acc, 0.f);
    }
    __syncthreads();

    float pr = (i < 64) ? h2s[i] * f3_w[i] : 0.f;
#pragma unroll
    for (int off = 16; off; off >>= 1) pr += __shfl_xor_sync(0xffffffffu, pr, off);
    if ((i & 31) == 0) rs[i >> 5] = pr;
    __syncthreads();
    if (i == 0) out[b] = rs[0] + rs[1] + f3_b[0];
}

// ============================================================================
extern "C" void kernel_launch(void* const* d_in, const int* in_sizes, int n_in,
                              void* d_out, int out_size) {
    (void)in_sizes; (void)n_in; (void)out_size;
    const float* x        = (const float*)d_in[0];
    const float* Wp       = (const float*)d_in[1];
    const float* bp       = (const float*)d_in[2];
    const float* Wrec     = (const float*)d_in[3];
    const float* Win_w    = (const float*)d_in[4];
    const float* Win_b    = (const float*)d_in[5];
    const float* cbias    = (const float*)d_in[6];
    const float* tau_base = (const float*)d_in[7];
    const float* vg1_w    = (const float*)d_in[8];
    const float* vg1_b    = (const float*)d_in[9];
    const float* vg2_w    = (const float*)d_in[10];
    const float* vg2_b    = (const float*)d_in[11];
    const float* proj_w   = (const float*)d_in[12];
    const float* proj_b   = (const float*)d_in[13];
    const float* f1_w     = (const float*)d_in[14];
    const float* f1_b     = (const float*)d_in[15];
    const float* f2_w     = (const float*)d_in[16];
    const float* f2_b     = (const float*)d_in[17];
    const float* f3_w     = (const float*)d_in[18];
    const float* f3_b     = (const float*)d_in[19];
    float* out = (float*)d_out;

    k_xp  <<<BTn / 32, 128>>>(x, Wp, bp);
    k_inp <<<dim3(BTn / 64, Sn), 128>>>(Win_w, Win_b, cbias);
    k_itau<<<dim3(BTn / 64, Sn), 128>>>(vg1_w, vg1_b, vg2_w, vg2_b, tau_base);
    k_scan<<<Sn * Bn, 128>>>(Wrec);
    k_head<<<Bn, 128>>>(proj_w, proj_b, f1_w, f1_b, f2_w, f2_b, f3_w, f3_b, out);
}

// round 15
// speedup vs baseline: 1.0621x; 1.0621x over previous
#include <cuda_runtime.h>
#include <math.h>
#include <cstdint>

// ---------------- problem constants ----------------
#define Bn   256
#define Tn   512
#define INn  32
#define Hn   128
#define Sn   4
#define HQn  32
#define BTn  (Bn*Tn)          // 131072 positions
#define DTC  0.1f
#define LOG2E 1.4426950408889634f

typedef unsigned long long u64;
typedef unsigned int u32;
typedef ulonglong2 u64x2;

// ---------------- scratch (static device globals; no allocation) ----------------
__device__ float g_xp  [(size_t)BTn*Hn];        //  64 MB
__device__ float g_inp [(size_t)Sn*BTn*Hn];     // 268 MB (pair-interleaved channels)
__device__ float g_itau[(size_t)Sn*BTn*Hn];     // 268 MB (pair-interleaved channels)
__device__ float g_hT  [Sn*Bn*Hn];

// ---------------- packed fp32x2 helpers (Blackwell FFMA2) ----------------
__device__ __forceinline__ void ffma2(u64 &d, u64 a, u64 b) {
    asm("fma.rn.f32x2 %0, %1, %2, %0;" : "+l"(d) : "l"(a), "l"(b));
}
__device__ __forceinline__ void add2(u64 &d, u64 a) {
    asm("add.rn.f32x2 %0, %0, %1;" : "+l"(d) : "l"(a));
}
__device__ __forceinline__ float hsum1(u64 a0) {
    float x0, y0;
    asm("mov.b64 {%0,%1}, %2;" : "=f"(x0), "=f"(y0) : "l"(a0));
    return x0 + y0;
}
__device__ __forceinline__ float hsum2p(u64 a0, u64 a1) {
    add2(a0, a1);
    return hsum1(a0);
}
__device__ __forceinline__ float hsum4(u64 a0, u64 a1, u64 a2, u64 a3) {
    add2(a0, a1); add2(a2, a3); add2(a0, a2);
    return hsum1(a0);
}

// ---------------- fast approx math ----------------
__device__ __forceinline__ float fast_ex2(float x) {
    float r; asm("ex2.approx.f32 %0, %1;" : "=f"(r) : "f"(x)); return r;
}
__device__ __forceinline__ float fast_rcp(float x) {
    float r; asm("rcp.approx.f32 %0, %1;" : "=f"(r) : "f"(x)); return r;
}
__device__ __forceinline__ float fast_sqrt(float x) {
    float r; asm("sqrt.approx.f32 %0, %1;" : "=f"(r) : "f"(x)); return r;
}
// single-op MUFU tanh (sm_75+): ~16cy, abs err ~6e-4
__device__ __forceinline__ float tanh_mufu(float x) {
    float r; asm("tanh.approx.f32 %0, %1;" : "=f"(r) : "f"(x)); return r;
}
__device__ __forceinline__ float fast_sigmoid(float z) {
    float zc = fminf(fmaxf(z, -30.f), 30.f);
    return fast_rcp(1.f + fast_ex2(-zc * LOG2E));
}

// ---------------- cp.async helpers (8B, ca) ----------------
__device__ __forceinline__ void cp_async8(u32 dst_smem, const void* src) {
    asm volatile("cp.async.ca.shared.global [%0], [%1], 8;" :: "r"(dst_smem), "l"(src));
}
__device__ __forceinline__ void cp_commit() {
    asm volatile("cp.async.commit_group;");
}
__device__ __forceinline__ void cp_wait0() {
    asm volatile("cp.async.wait_group 0;" ::: "memory");
}

// ============================================================================
// K1: x_proj[pos, i] = x[pos, :32] @ Wp[i, :32] + bp[i]
// ============================================================================
__global__ void __launch_bounds__(128) k_xp(const float* __restrict__ x,
                                            const float* __restrict__ Wp,
                                            const float* __restrict__ bp) {
    const int i  = threadIdx.x;
    const int p0 = blockIdx.x * 32;
    __shared__ __align__(16) float xs[32][INn];

    const float4* src = (const float4*)(x + (size_t)p0 * INn);
    float4* dst = (float4*)&xs[0][0];
    dst[i]       = src[i];
    dst[i + 128] = src[i + 128];

    u64 w[16];
    {
        const u64x2* wq = (const u64x2*)(Wp + (size_t)i * INn);
#pragma unroll
        for (int m = 0; m < 8; m++) { u64x2 v = wq[m]; w[2*m] = v.x; w[2*m+1] = v.y; }
    }
    const float bias = bp[i];
    __syncthreads();

#pragma unroll 4
    for (int p = 0; p < 32; p++) {
        const u64x2* xq = (const u64x2*)&xs[p][0];
        u64 a0 = 0ull, a1 = 0ull, a2 = 0ull, a3 = 0ull;
#pragma unroll
        for (int m = 0; m < 8; m += 2) {
            u64x2 p0v = xq[m], p1v = xq[m+1];
            ffma2(a0, w[2*m],   p0v.x); ffma2(a1, w[2*m+1], p0v.y);
            ffma2(a2, w[2*m+2], p1v.x); ffma2(a3, w[2*m+3], p1v.y);
        }
        g_xp[(size_t)(p0 + p) * Hn + i] = hsum4(a0, a1, a2, a3) + bias;
    }
}

// ============================================================================
// K2: inp drive, split-K dual-channel (measured best, R9). Pair-interleaved
// output: slots (2c, 2c+1) hold channels (c, c+64).
// ============================================================================
__global__ void __launch_bounds__(128) k_inp(const float* __restrict__ Win_w,
                                             const float* __restrict__ Win_b,
                                             const float* __restrict__ cbias) {
    const int i    = threadIdx.x;
    const int s    = blockIdx.y;
    const int p0   = blockIdx.x * 64;
    const int wd   = i >> 5;
    const int lane = i & 31;
    const int half = lane >> 4;
    const int c    = wd * 16 + (lane & 15);   // 0..63
    __shared__ __align__(16) float xs[64][Hn];   // 32 KB

    const float4* src = (const float4*)(g_xp + (size_t)p0 * Hn);
    float4* dst = (float4*)&xs[0][0];
#pragma unroll
    for (int r = i; r < 2048; r += 128) dst[r] = src[r];

    u64 wA[32], wB[32];
    {
        const u64x2* wqA = (const u64x2*)(Win_w + ((size_t)s * Hn + c) * Hn + half * 64);
        const u64x2* wqB = (const u64x2*)(Win_w + ((size_t)s * Hn + c + 64) * Hn + half * 64);
#pragma unroll
        for (int m = 0; m < 16; m++) { u64x2 v = wqA[m]; wA[2*m] = v.x; wA[2*m+1] = v.y; }
#pragma unroll
        for (int m = 0; m < 16; m++) { u64x2 v = wqB[m]; wB[2*m] = v.x; wB[2*m+1] = v.y; }
    }
    const float biasA = Win_b[s * Hn + c]      + cbias[s * Hn + c];
    const float biasB = Win_b[s * Hn + c + 64] + cbias[s * Hn + c + 64];
    __syncthreads();

    float* outp = g_inp + ((size_t)s * BTn + p0) * Hn + 2 * c;
#pragma unroll 2
    for (int p = 0; p < 64; p++) {
        const u64x2* xq = (const u64x2*)(&xs[p][half * 64]);
        u64 a0 = 0ull, a1 = 0ull, b0 = 0ull, b1 = 0ull;
#pragma unroll
        for (int m = 0; m < 16; m++) {
            const u64x2 hv = xq[m];
            ffma2(a0, wA[2*m],   hv.x); ffma2(b0, wB[2*m],   hv.x);
            ffma2(a1, wA[2*m+1], hv.y); ffma2(b1, wB[2*m+1], hv.y);
        }
        float pA = hsum2p(a0, a1);
        float pB = hsum2p(b0, b1);
        pA += __shfl_xor_sync(0xffffffffu, pA, 16);
        pB += __shfl_xor_sync(0xffffffffu, pB, 16);
        if (half == 0) {
            float2 v = make_float2(pA + biasA, pB + biasB);
            __stwt((float2*)(outp + (size_t)p * Hn), v);
        }
    }
}

// ============================================================================
// K3: volatility gate -> itau (R9 structure, pair-interleaved output).
// ============================================================================
__global__ void __launch_bounds__(128) k_itau(const float* __restrict__ v1w,
                                              const float* __restrict__ v1b,
                                              const float* __restrict__ v2w,
                                              const float* __restrict__ v2b,
                                              const float* __restrict__ tau_base) {
    const int i    = threadIdx.x;
    const int s    = blockIdx.y;
    const int p0   = blockIdx.x * 64;
    const int wd   = i >> 5;
    const int lane = i & 31;
    __shared__ __align__(16) float xs[64][Hn];   // 32 KB
    __shared__ __align__(16) float gs[64][HQn];  //  8 KB

    const float4* src = (const float4*)(g_xp + (size_t)p0 * Hn);
    float4* dst = (float4*)&xs[0][0];
#pragma unroll
    for (int r = i; r < 2048; r += 128) dst[r] = src[r];
    __syncthreads();

    // ---- stage 1: g = relu(xp @ v1w.T + v1b), split-K dual-output ----
    {
        const int half = lane >> 4;
        const int q    = lane & 15;
        u64 wA[32], wB[32];
        const u64x2* wqA = (const u64x2*)(v1w + ((size_t)s * HQn + q) * Hn + half * 64);
        const u64x2* wqB = (const u64x2*)(v1w + ((size_t)s * HQn + q + 16) * Hn + half * 64);
#pragma unroll
        for (int m = 0; m < 16; m++) { u64x2 v = wqA[m]; wA[2*m] = v.x; wA[2*m+1] = v.y; }
#pragma unroll
        for (int m = 0; m < 16; m++) { u64x2 v = wqB[m]; wB[2*m] = v.x; wB[2*m+1] = v.y; }
        const float b1A = v1b[s * HQn + q];
        const float b1B = v1b[s * HQn + q + 16];
#pragma unroll 2
        for (int pp = 0; pp < 16; pp++) {
            const int p = wd * 16 + pp;
            const u64x2* xq = (const u64x2*)(&xs[p][half * 64]);
            u64 a0 = 0ull, a1 = 0ull, b0 = 0ull, b1 = 0ull;
#pragma unroll
            for (int m = 0; m < 16; m++) {
                const u64x2 hv = xq[m];
                ffma2(a0, wA[2*m],   hv.x); ffma2(b0, wB[2*m],   hv.x);
                ffma2(a1, wA[2*m+1], hv.y); ffma2(b1, wB[2*m+1], hv.y);
            }
            float pA = hsum2p(a0, a1);
            float pB = hsum2p(b0, b1);
            pA += __shfl_xor_sync(0xffffffffu, pA, 16);
            pB += __shfl_xor_sync(0xffffffffu, pB, 16);
            if (half == 0) {
                gs[p][q]      = fmaxf(pA + b1A, 0.f);
                gs[p][q + 16] = fmaxf(pB + b1B, 0.f);
            }
        }
    }
    __syncthreads();

    // ---- stage 2: vol -> itau (channel-permuted, coalesced store) ----
    {
        const int c = ((i & 1) << 6) | (i >> 1);
        u64 w2[16];
        const u64x2* wq = (const u64x2*)(v2w + ((size_t)s * Hn + c) * HQn);
#pragma unroll
        for (int m = 0; m < 8; m++) { u64x2 v = wq[m]; w2[2*m] = v.x; w2[2*m+1] = v.y; }
        const float b2 = v2b[s * Hn + c];
        const float tb = tau_base[s * Hn + c];
        float* outp = g_itau + ((size_t)s * BTn + p0) * Hn + i;
#pragma unroll 2
        for (int p = 0; p < 64; p++) {
            const u64x2* gq = (const u64x2*)&gs[p][0];
            u64 a0 = 0ull, a1 = 0ull, a2 = 0ull, a3 = 0ull;
#pragma unroll
            for (int m = 0; m < 8; m += 2) {
                u64x2 p0v = gq[m], p1v = gq[m+1];
                ffma2(a0, w2[2*m],   p0v.x); ffma2(a1, w2[2*m+1], p0v.y);
                ffma2(a2, w2[2*m+2], p1v.x); ffma2(a3, w2[2*m+3], p1v.y);
            }
            const float z   = hsum4(a0, a1, a2, a3) + b2;
            const float vol = fast_sigmoid(z);
            float tau = tb * (0.2f + 1.8f * (1.f - vol));
            tau = fminf(fmaxf(tau, 0.1f), 10.f);
            __stwt(outp + (size_t)p * Hn, 1.f / tau);
        }
    }
}

// ---- scan step halves (macros bind per-row state) ----
// P1: matvec over row's h -> dh + norm partial into red (dh kept in regs)
#define P1_STEP(HS, RED, INP, ITAU, DH1, DH2, H1, H2)                        \
{                                                                            \
    const u64x2* hq_ = (const u64x2*)((HS) + half * 64);                     \
    u64 a0_ = 0ull, a1_ = 0ull, b0_ = 0ull, b1_ = 0ull;                      \
    _Pragma("unroll")                                                        \
    for (int m_ = 0; m_ < 16; m_++) {                                        \
        const u64x2 hv_ = hq_[m_];                                           \
        ffma2(a0_, w1[2*m_],   hv_.x); ffma2(b0_, w2[2*m_],   hv_.x);        \
        ffma2(a1_, w1[2*m_+1], hv_.y); ffma2(b1_, w2[2*m_+1], hv_.y);        \
    }                                                                        \
    float p1_ = hsum2p(a0_, a1_);                                            \
    float p2_ = hsum2p(b0_, b1_);                                            \
    p1_ += __shfl_xor_sync(0xffffffffu, p1_, 16);                            \
    p2_ += __shfl_xor_sync(0xffffffffu, p2_, 16);                            \
    DH1 = (tanh_mufu(p1_ + (INP).x) - (H1)) * (ITAU).x;                      \
    DH2 = (tanh_mufu(p2_ + (INP).y) - (H2)) * (ITAU).y;                      \
    float sq_ = fmaf(DH1, DH1, DH2 * DH2);                                   \
    sq_ += __shfl_xor_sync(0xffffffffu, sq_, 1);                             \
    sq_ += __shfl_xor_sync(0xffffffffu, sq_, 2);                             \
    sq_ += __shfl_xor_sync(0xffffffffu, sq_, 4);                             \
    sq_ += __shfl_xor_sync(0xffffffffu, sq_, 8);                             \
    if (lane == 0) (RED)[wid] = sq_;                                         \
}

// P2: norm total -> sc -> h update + publish
#define P2_STEP(HS, RED, DH1, DH2, H1, H2)                                   \
{                                                                            \
    const float4 r_ = *(const float4*)(RED);                                 \
    const float mag_ = fast_sqrt((r_.x + r_.y) + (r_.z + r_.w));             \
    const float sc_  = DTC * fast_rcp(fmaf(0.2f, mag_, 1.f));                \
    H1 = fmaf(sc_, DH1, H1);                                                 \
    H2 = fmaf(sc_, DH2, H2);                                                 \
    if (half == 0) { (HS)[cc] = H1; (HS)[cc + 64] = H2; }                    \
}

// ============================================================================
// K4: liquid-cell scan, STAGGERED dual-row. One CTA = 2 rows, shared Wrec.
// Each step = P1 (matvec->dh->red) | barrier | P2 (sc->h update). Rows run
// half-step out of phase: segment X = {P2_A(j), P1_B(j)}; segment Y =
// {P2_B(j), P1_A(j+1)}. Every barrier segment contains a full independent
// matvec -> one row's norm/barrier latency hides under the other's FFMA
// stream; barriers per row-step halve (2 -> 1). Drive staged in smem via
// cp.async double-buffer; wait->barrier->read ordering is explicit.
// ============================================================================
__global__ void __launch_bounds__(128, 3) k_scan(const float* __restrict__ Wrec) {
    const int bid  = blockIdx.x;              // 0..511
    const int s    = 3 - (bid >> 7);          // heavy scale first (LPT)
    const int bp   = bid & 127;
    const int t    = threadIdx.x;
    const int wid  = t >> 5;
    const int lane = t & 31;
    const int half = lane >> 4;                 // K-half
    const int cc   = wid * 16 + (lane & 15);    // 0..63

    __shared__ __align__(16) float h_sA[Hn];
    __shared__ __align__(16) float h_sB[Hn];
    __shared__ __align__(16) float redA[4];
    __shared__ __align__(16) float redB[4];
    __shared__ __align__(16) float2 drv[2][4][64];  // [buf][inpA,inpB,itauA,itauB][cc]

    // shared Wrec half-rows (channels cc, cc+64)
    u64 w1[32], w2[32];
    {
        const u64x2* wq1 = (const u64x2*)(Wrec + ((size_t)s * Hn + cc) * Hn + half * 64);
        const u64x2* wq2 = (const u64x2*)(Wrec + ((size_t)s * Hn + cc + 64) * Hn + half * 64);
#pragma unroll
        for (int m = 0; m < 16; m++) { u64x2 v = wq1[m]; w1[2*m] = v.x; w1[2*m+1] = v.y; }
#pragma unroll
        for (int m = 0; m < 16; m++) { u64x2 v = wq2[m]; w2[2*m] = v.x; w2[2*m+1] = v.y; }
    }

    const size_t rowA = (size_t)(s * Bn + 2 * bp);
    const float2* gIA = (const float2*)g_inp  + rowA * Tn * 64 + cc;
    const float2* gTA = (const float2*)g_itau + rowA * Tn * 64 + cc;

    const u32 drv_base = (u32)__cvta_generic_to_shared(&drv[0][0][0]);
    const u32 my_a0 = drv_base + (half == 0 ? 0u : 2u) * 512u + (u32)cc * 8u;
    const u32 my_a1 = my_a0 + 512u;
    const float2* my_s0 = (half == 0) ? gIA : gTA;        // row A source
    const float2* my_s1 = my_s0 + (size_t)Tn * 64;        // row B source

    // stage tt=0 and tt=1
    cp_async8(my_a0, my_s0);
    cp_async8(my_a1, my_s1);
    cp_commit();
    cp_async8(my_a0 + 2048u, my_s0 + 64);
    cp_async8(my_a1 + 2048u, my_s1 + 64);
    cp_commit();

    float hA1 = 0.f, hA2 = 0.f, hB1 = 0.f, hB2 = 0.f;
    float dhA1 = 0.f, dhA2 = 0.f, dhB1 = 0.f, dhB2 = 0.f;
    h_sA[t] = 0.f;
    h_sB[t] = 0.f;
    const int nsteps = 3 + 2 * s;
    const int S = Tn * nsteps;

    cp_wait0();
    __syncthreads();

    float2 iA = drv[0][0][cc], iB = drv[0][1][cc];
    float2 tA = drv[0][2][cc], tB = drv[0][3][cc];
    int kk = 0, tt = 0;

    // prologue: A's first P1
    P1_STEP(h_sA, redA, iA, tA, dhA1, dhA2, hA1, hA2);
    __syncthreads();

    for (int j = 0; j < S; j++) {
        // ---- segment X: P2_A(j), P1_B(j) ----
        P2_STEP(h_sA, redA, dhA1, dhA2, hA1, hA2);
        P1_STEP(h_sB, redB, iB, tB, dhB1, dhB2, hB1, hB2);
        if (kk + 1 == nsteps) cp_wait0();   // uniform; completes staged buffer
        __syncthreads();

        // ---- segment Y: P2_B(j), [rotate], P1_A(j+1) ----
        P2_STEP(h_sB, redB, dhB1, dhB2, hB1, hB2);
        if (j + 1 < S) {
            if (kk + 1 == nsteps) {
                kk = 0; tt++;
                const int bsel = tt & 1;
                iA = drv[bsel][0][cc]; iB = drv[bsel][1][cc];
                tA = drv[bsel][2][cc]; tB = drv[bsel][3][cc];
                if (tt + 1 < Tn) {
                    const u32 off = (u32)((tt + 1) & 1) * 2048u;
                    const size_t goff = (size_t)(tt + 1) * 64;
                    cp_async8(my_a0 + off, my_s0 + goff);
                    cp_async8(my_a1 + off, my_s1 + goff);
                    cp_commit();
                }
            } else {
                kk++;
            }
            P1_STEP(h_sA, redA, iA, tA, dhA1, dhA2, hA1, hA2);
        }
        __syncthreads();
    }

    if (half == 0) {
        float* o = g_hT + rowA * Hn;
        o[cc]           = hA1;
        o[cc + 64]      = hA2;
        o[Hn + cc]      = hB1;
        o[Hn + cc + 64] = hB2;
    }
}

// ============================================================================
// K5: projection heads + fusion MLP. One CTA per batch row.
// ============================================================================
__global__ void __launch_bounds__(128) k_head(const float* __restrict__ proj_w,
                                              const float* __restrict__ proj_b,
                                              const float* __restrict__ f1_w,
                                              const float* __restrict__ f1_b,
                                              const float* __restrict__ f2_w,
                                              const float* __restrict__ f2_b,
                                              const float* __restrict__ f3_w,
                                              const float* __restrict__ f3_b,
                                              float* __restrict__ out) {
    const int b = blockIdx.x;
    const int i = threadIdx.x;
    __shared__ float fs[Hn];
    __shared__ float h1s[Hn];
    __shared__ float h2s[64];
    __shared__ float rs[4];

    {
        const int s = i >> 5, q = i & 31;
        const float* hrow = g_hT + (size_t)(s * Bn + b) * Hn;
        const float* pw   = proj_w + (size_t)(s * 32 + q) * Hn;
        float acc = proj_b[s * 32 + q];
#pragma unroll 8
        for (int j = 0; j < Hn; j++) acc += hrow[j] * pw[j];
        fs[i] = acc;
    }
    __syncthreads();

    {
        const float* w1 = f1_w + (size_t)i * Hn;
        float acc = f1_b[i];
#pragma unroll 8
        for (int j = 0; j < Hn; j++) acc += fs[j] * w1[j];
        h1s[i] = fmaxf(acc, 0.f);
    }
    __syncthreads();

    if (i < 64) {
        const float* w2 = f2_w + (size_t)i * Hn;
        float acc = f2_b[i];
#pragma unroll 8
        for (int j = 0; j < Hn; j++) acc += h1s[j] * w2[j];
        h2s[i] = fmaxf(acc, 0.f);
    }
    __syncthreads();

    float pr = (i < 64) ? h2s[i] * f3_w[i] : 0.f;
#pragma unroll
    for (int off = 16; off; off >>= 1) pr += __shfl_xor_sync(0xffffffffu, pr, off);
    if ((i & 31) == 0) rs[i >> 5] = pr;
    __syncthreads();
    if (i == 0) out[b] = rs[0] + rs[1] + f3_b[0];
}

// ============================================================================
extern "C" void kernel_launch(void* const* d_in, const int* in_sizes, int n_in,
                              void* d_out, int out_size) {
    (void)in_sizes; (void)n_in; (void)out_size;
    const float* x        = (const float*)d_in[0];
    const float* Wp       = (const float*)d_in[1];
    const float* bp       = (const float*)d_in[2];
    const float* Wrec     = (const float*)d_in[3];
    const float* Win_w    = (const float*)d_in[4];
    const float* Win_b    = (const float*)d_in[5];
    const float* cbias    = (const float*)d_in[6];
    const float* tau_base = (const float*)d_in[7];
    const float* vg1_w    = (const float*)d_in[8];
    const float* vg1_b    = (const float*)d_in[9];
    const float* vg2_w    = (const float*)d_in[10];
    const float* vg2_b    = (const float*)d_in[11];
    const float* proj_w   = (const float*)d_in[12];
    const float* proj_b   = (const float*)d_in[13];
    const float* f1_w     = (const float*)d_in[14];
    const float* f1_b     = (const float*)d_in[15];
    const float* f2_w     = (const float*)d_in[16];
    const float* f2_b     = (const float*)d_in[17];
    const float* f3_w     = (const float*)d_in[18];
    const float* f3_b     = (const float*)d_in[19];
    float* out = (float*)d_out;

    k_xp  <<<BTn / 32, 128>>>(x, Wp, bp);
    k_inp <<<dim3(BTn / 64, Sn), 128>>>(Win_w, Win_b, cbias);
    k_itau<<<dim3(BTn / 64, Sn), 128>>>(vg1_w, vg1_b, vg2_w, vg2_b, tau_base);
    k_scan<<<Sn * Bn / 2, 128>>>(Wrec);
    k_head<<<Bn, 128>>>(proj_w, proj_b, f1_w, f1_b, f2_w, f2_b, f3_w, f3_b, out);
}